// round 1
// baseline (speedup 1.0000x reference)
#include <cuda_runtime.h>
#include <math.h>
#include <stdint.h>

#define NNODES 50000
#define NEDGES 800000
#define HID 128
#define EDIM 16
#define NL 3
#define NG 256
#define BN_EPS 1e-5f

// ------------------------- scratch (static device globals) -------------------
__device__ float g_h[NNODES * HID];          // node hidden state
__device__ float g_p[NNODES * HID];          // P = h@W1a + b1
__device__ float g_s[NNODES * HID];          // scatter-sum of relu messages
__device__ float g_gi[NNODES * 3 * HID];     // GRU input gates
__device__ float g_gh[NNODES * 3 * HID];     // GRU hidden gates
__device__ float g_deg[NNODES];              // in-degree (float)
__device__ float g_w2i[NL * HID * 3 * HID];  // W2 @ wih^T  [l][k][g]
__device__ float g_c2i[NL * 3 * HID];        // b2 @ wih^T  [l][g]
__device__ float g_packb[NL * HID * 512];    // [W1a | whh^T] packed [l][k][512]
__device__ float g_packbias[NL * 512];       // [b1 | bhh]
__device__ float g_zsum[NG * HID];
__device__ unsigned g_zmaxk[NG * HID];
__device__ float g_cnt[NG];

// ------------------------- packed f32x2 helpers ------------------------------
__device__ __forceinline__ unsigned long long pk2(float lo, float hi) {
    unsigned long long r;
    asm("mov.b64 %0, {%1, %2};" : "=l"(r) : "f"(lo), "f"(hi));
    return r;
}
__device__ __forceinline__ void unpk2(unsigned long long v, float& lo, float& hi) {
    asm("mov.b64 {%0, %1}, %2;" : "=f"(lo), "=f"(hi) : "l"(v));
}
#define FMA2(acc, a, b) asm("fma.rn.f32x2 %0, %1, %2, %0;" : "+l"(acc) : "l"(a), "l"(b))

__device__ __forceinline__ float sigm(float x) { return 1.f / (1.f + __expf(-x)); }

// ------------------------- generic K=128 SGEMM -------------------------------
// C[M,N] = A[M,128] @ B[128,N] (+bias[N]) (+rowscale[m]*rowvec[n]) (relu?)
// Columns [0,c0cols) -> C0 (ld=c0cols); columns >= c0cols -> C1 (ld=N-c0cols).
#define BM 128
#define BN 64
#define BK 32
__global__ __launch_bounds__(256) void sgemm128(
    const float* __restrict__ A, const float* __restrict__ B,
    int M, int N, const float* __restrict__ bias,
    float* __restrict__ C0, int c0cols, float* __restrict__ C1,
    const float* __restrict__ rowscale, const float* __restrict__ rowvec,
    int do_relu)
{
    __shared__ float As[BK][BM + 4];
    __shared__ float Bs[BK][BN];

    int m0 = blockIdx.x * BM;
    int n0 = blockIdx.y * BN;
    int t = threadIdx.x;
    int rg = t >> 4;   // 0..15 row group (8 rows each)
    int cg = t & 15;   // 0..15 col group (4 cols each)

    unsigned long long acc[4][4];
#pragma unroll
    for (int p = 0; p < 4; p++)
#pragma unroll
        for (int j = 0; j < 4; j++) acc[p][j] = 0ull;

    for (int k0 = 0; k0 < 128; k0 += BK) {
        // load A tile: 128 rows x 32 cols = 1024 float4-groups? -> 1024 float4 / 4 per thread
#pragma unroll
        for (int i = 0; i < 4; i++) {
            int id = t + i * 256;        // 0..1023
            int row = id >> 3;           // 0..127
            int kk = (id & 7) * 4;       // 0..28
            float4 v = make_float4(0.f, 0.f, 0.f, 0.f);
            int gm = m0 + row;
            if (gm < M) v = *(const float4*)(A + gm * 128 + k0 + kk);
            As[kk + 0][row] = v.x;
            As[kk + 1][row] = v.y;
            As[kk + 2][row] = v.z;
            As[kk + 3][row] = v.w;
        }
        // load B tile: 32 rows x 64 cols = 512 float4 / 2 per thread
#pragma unroll
        for (int i = 0; i < 2; i++) {
            int id = t + i * 256;        // 0..511
            int row = id >> 4;           // 0..31
            int nn = (id & 15) * 4;
            *(float4*)&Bs[row][nn] = *(const float4*)(B + (k0 + row) * N + n0 + nn);
        }
        __syncthreads();
#pragma unroll
        for (int k = 0; k < BK; k++) {
            ulonglong2 a01 = *(const ulonglong2*)&As[k][rg * 8];
            ulonglong2 a23 = *(const ulonglong2*)&As[k][rg * 8 + 4];
            float4 b = *(const float4*)&Bs[k][cg * 4];
            unsigned long long b0 = pk2(b.x, b.x);
            unsigned long long b1 = pk2(b.y, b.y);
            unsigned long long b2 = pk2(b.z, b.z);
            unsigned long long b3 = pk2(b.w, b.w);
            FMA2(acc[0][0], a01.x, b0); FMA2(acc[0][1], a01.x, b1);
            FMA2(acc[0][2], a01.x, b2); FMA2(acc[0][3], a01.x, b3);
            FMA2(acc[1][0], a01.y, b0); FMA2(acc[1][1], a01.y, b1);
            FMA2(acc[1][2], a01.y, b2); FMA2(acc[1][3], a01.y, b3);
            FMA2(acc[2][0], a23.x, b0); FMA2(acc[2][1], a23.x, b1);
            FMA2(acc[2][2], a23.x, b2); FMA2(acc[2][3], a23.x, b3);
            FMA2(acc[3][0], a23.y, b0); FMA2(acc[3][1], a23.y, b1);
            FMA2(acc[3][2], a23.y, b2); FMA2(acc[3][3], a23.y, b3);
        }
        __syncthreads();
    }

    // epilogue
    float vals[8][4];
#pragma unroll
    for (int p = 0; p < 4; p++)
#pragma unroll
        for (int j = 0; j < 4; j++) unpk2(acc[p][j], vals[2 * p][j], vals[2 * p + 1][j]);

    int nbase = n0 + cg * 4;
    float bv[4] = {0.f, 0.f, 0.f, 0.f};
    float rv[4] = {0.f, 0.f, 0.f, 0.f};
    if (bias) {
#pragma unroll
        for (int j = 0; j < 4; j++) bv[j] = bias[nbase + j];
    }
    if (rowvec) {
#pragma unroll
        for (int j = 0; j < 4; j++) rv[j] = rowvec[nbase + j];
    }
#pragma unroll
    for (int i = 0; i < 8; i++) {
        int gm = m0 + rg * 8 + i;
        if (gm >= M) break;
        float rs = rowscale ? rowscale[gm] : 0.f;
        float o[4];
#pragma unroll
        for (int j = 0; j < 4; j++) {
            float v = vals[i][j] + bv[j] + rs * rv[j];
            if (do_relu) v = fmaxf(v, 0.f);
            o[j] = v;
        }
        float4 o4 = make_float4(o[0], o[1], o[2], o[3]);
        if (nbase < c0cols) {
            *(float4*)(C0 + (size_t)gm * c0cols + nbase) = o4;
        } else {
            *(float4*)(C1 + (size_t)gm * (N - c0cols) + (nbase - c0cols)) = o4;
        }
    }
}

// ------------------------- small prep kernels --------------------------------
__global__ void zero_misc_kernel() {
    int i = blockIdx.x * blockDim.x + threadIdx.x;
    if (i < NNODES) g_deg[i] = 0.f;
    if (i < NG * HID) { g_zsum[i] = 0.f; g_zmaxk[i] = 0u; }
    if (i < NG) g_cnt[i] = 0.f;
}

__global__ void zero_s_kernel() {
    int i = blockIdx.x * blockDim.x + threadIdx.x;
    if (i < NNODES * HID / 4) ((float4*)g_s)[i] = make_float4(0.f, 0.f, 0.f, 0.f);
}

__global__ void deg_kernel(const int* __restrict__ dst) {
    int e = blockIdx.x * blockDim.x + threadIdx.x;
    if (e < NEDGES) atomicAdd(&g_deg[dst[e]], 1.0f);
}

// pack B = [W1a | whh^T] and bias = [b1 | bhh]
__global__ void pack_kernel(const float* __restrict__ msg_w1, const float* __restrict__ msg_b1,
                            const float* __restrict__ whh, const float* __restrict__ bhh) {
    int idx = blockIdx.x * blockDim.x + threadIdx.x;
    if (idx < NL * HID * 512) {
        int l = idx / (HID * 512);
        int r = idx % (HID * 512);
        int k = r / 512;
        int c = r % 512;
        float v;
        if (c < HID) v = msg_w1[l * 144 * HID + k * HID + c];
        else {
            int g = c - HID;
            v = whh[l * 384 * HID + g * HID + k];
        }
        g_packb[idx] = v;
    }
    if (idx < NL * 512) {
        int l = idx / 512, c = idx % 512;
        g_packbias[idx] = (c < HID) ? msg_b1[l * HID + c] : bhh[l * 384 + (c - HID)];
    }
}

// W2i[l][k][g] = sum_j W2[l][k][j] * wih[l][g][j]
__global__ void w2i_kernel(const float* __restrict__ msg_w2, const float* __restrict__ wih) {
    __shared__ float w2row[HID];
    int b = blockIdx.x;          // l*HID + k
    int l = b / HID, k = b % HID;
    int g = threadIdx.x;         // 0..383
    if (g < HID) w2row[g] = msg_w2[l * HID * HID + k * HID + g];
    __syncthreads();
    const float* wr = wih + l * 384 * HID + g * HID;
    float acc = 0.f;
#pragma unroll 8
    for (int j = 0; j < HID; j++) acc += w2row[j] * __ldg(wr + j);
    g_w2i[(l * HID + k) * 384 + g] = acc;
}

// c2i[l][g] = sum_j b2[l][j] * wih[l][g][j]
__global__ void c2i_kernel(const float* __restrict__ msg_b2, const float* __restrict__ wih) {
    int idx = blockIdx.x * blockDim.x + threadIdx.x;
    if (idx >= NL * 384) return;
    int l = idx / 384, g = idx % 384;
    const float* wr = wih + l * 384 * HID + g * HID;
    const float* b2 = msg_b2 + l * HID;
    float acc = 0.f;
#pragma unroll 8
    for (int j = 0; j < HID; j++) acc += b2[j] * __ldg(wr + j);
    g_c2i[idx] = acc;
}

// ------------------------- edge message + scatter ----------------------------
// per edge: m = relu(P[src] + ea @ W1b); atomic float4 add into S[dst]
__global__ __launch_bounds__(256) void edge_kernel(
    const int* __restrict__ src, const int* __restrict__ dst,
    const float* __restrict__ ea, const float* __restrict__ w1b)
{
    int lane = threadIdx.x & 31;
    int warp = (blockIdx.x * blockDim.x + threadIdx.x) >> 5;
    int nwarp = (gridDim.x * blockDim.x) >> 5;

    unsigned long long w0[16], w1[16];
#pragma unroll
    for (int t = 0; t < 16; t++) {
        float4 w = *(const float4*)(w1b + t * HID + lane * 4);
        w0[t] = pk2(w.x, w.y);
        w1[t] = pk2(w.z, w.w);
    }

    for (int e = warp; e < NEDGES; e += nwarp) {
        int s = __ldg(src + e);
        int d = __ldg(dst + e);
        const float4* eap = (const float4*)(ea + (size_t)e * EDIM);
        float4 e0 = __ldg(eap + 0), e1 = __ldg(eap + 1);
        float4 e2 = __ldg(eap + 2), e3 = __ldg(eap + 3);
        ulonglong2 p2 = *(const ulonglong2*)(g_p + (size_t)s * HID + lane * 4);
        unsigned long long a0 = p2.x, a1 = p2.y;
        float ec[16] = {e0.x, e0.y, e0.z, e0.w, e1.x, e1.y, e1.z, e1.w,
                        e2.x, e2.y, e2.z, e2.w, e3.x, e3.y, e3.z, e3.w};
#pragma unroll
        for (int t = 0; t < 16; t++) {
            unsigned long long et = pk2(ec[t], ec[t]);
            FMA2(a0, w0[t], et);
            FMA2(a1, w1[t], et);
        }
        float x0, x1, x2, x3;
        unpk2(a0, x0, x1);
        unpk2(a1, x2, x3);
        float4 m = make_float4(fmaxf(x0, 0.f), fmaxf(x1, 0.f),
                               fmaxf(x2, 0.f), fmaxf(x3, 0.f));
        atomicAdd((float4*)(g_s + (size_t)d * HID) + lane, m);
    }
}

// ------------------------- GRU gates + BN + residual -------------------------
__global__ void gate_kernel(const float* __restrict__ gamma, const float* __restrict__ beta,
                            const float* __restrict__ mean, const float* __restrict__ var)
{
    int idx = blockIdx.x * blockDim.x + threadIdx.x;
    if (idx >= NNODES * (HID / 4)) return;
    int n = idx >> 5;
    int q = idx & 31;
    int j0 = q * 4;
    const float* gi = g_gi + (size_t)n * 384 + j0;
    const float* gh = g_gh + (size_t)n * 384 + j0;
    float4 gir = *(const float4*)(gi);
    float4 giz = *(const float4*)(gi + 128);
    float4 gin = *(const float4*)(gi + 256);
    float4 ghr = *(const float4*)(gh);
    float4 ghz = *(const float4*)(gh + 128);
    float4 ghn = *(const float4*)(gh + 256);
    float4 h4 = *(const float4*)(g_h + (size_t)n * HID + j0);

    float ir[4] = {gir.x, gir.y, gir.z, gir.w};
    float iz[4] = {giz.x, giz.y, giz.z, giz.w};
    float in_[4] = {gin.x, gin.y, gin.z, gin.w};
    float hr[4] = {ghr.x, ghr.y, ghr.z, ghr.w};
    float hz[4] = {ghz.x, ghz.y, ghz.z, ghz.w};
    float hn[4] = {ghn.x, ghn.y, ghn.z, ghn.w};
    float hv[4] = {h4.x, h4.y, h4.z, h4.w};
    float ov[4];
#pragma unroll
    for (int c = 0; c < 4; c++) {
        float r = sigm(ir[c] + hr[c]);
        float z = sigm(iz[c] + hz[c]);
        float nn = tanhf(in_[c] + r * hn[c]);
        float hnew = (1.f - z) * nn + z * hv[c];
        float gm = gamma[j0 + c], bt = beta[j0 + c];
        float mu = mean[j0 + c], vr = var[j0 + c];
        float bn = (hnew - mu) * rsqrtf(vr + BN_EPS) * gm + bt;
        ov[c] = hv[c] + bn;
    }
    *(float4*)(g_h + (size_t)n * HID + j0) = make_float4(ov[0], ov[1], ov[2], ov[3]);
}

// ------------------------- readout -------------------------------------------
__device__ __forceinline__ unsigned enc_f(float f) {
    unsigned u = __float_as_uint(f);
    return (u & 0x80000000u) ? ~u : (u | 0x80000000u);
}

__global__ void readout_kernel(const int* __restrict__ batch) {
    int lane = threadIdx.x & 31;
    int n = (blockIdx.x * blockDim.x + threadIdx.x) >> 5;
    if (n >= NNODES) return;
    int g = __ldg(batch + n);
    float4 v = *(const float4*)(g_h + (size_t)n * HID + lane * 4);
    atomicAdd((float4*)(g_zsum + (size_t)g * HID) + lane, v);
    unsigned* mk = g_zmaxk + (size_t)g * HID + lane * 4;
    atomicMax(mk + 0, enc_f(v.x));
    atomicMax(mk + 1, enc_f(v.y));
    atomicMax(mk + 2, enc_f(v.z));
    atomicMax(mk + 3, enc_f(v.w));
    if (lane == 0) atomicAdd(&g_cnt[g], 1.f);
}

__global__ void final_kernel(const float* __restrict__ ro_w, const float* __restrict__ ro_b,
                             float* __restrict__ out)
{
    int gph = blockIdx.x;   // 0..255
    int j = threadIdx.x;    // 0..127
    __shared__ float smean[HID], smax[HID];
    float cntv = g_cnt[gph];
    float inv = 1.f / fmaxf(cntv, 1.f);
    bool has = cntv > 0.f;
    if (j < HID) {
        smean[j] = g_zsum[gph * HID + j] * inv;
        unsigned k = g_zmaxk[gph * HID + j];
        float mx = (k & 0x80000000u) ? __uint_as_float(k & 0x7fffffffu) : __uint_as_float(~k);
        smax[j] = has ? mx : 0.f;
    }
    __syncthreads();
    float acc = ro_b[j];
#pragma unroll 4
    for (int k = 0; k < HID; k++) {
        acc += smean[k] * __ldg(ro_w + k * HID + j);
        acc += smax[k] * __ldg(ro_w + (HID + k) * HID + j);
    }
    out[gph * HID + j] = fmaxf(acc, 0.f);
}

// ------------------------- launch --------------------------------------------
extern "C" void kernel_launch(void* const* d_in, const int* in_sizes, int n_in,
                              void* d_out, int out_size)
{
    const float* x     = (const float*)d_in[0];
    const int*   eidx  = (const int*)d_in[1];
    const float* eattr = (const float*)d_in[2];
    const int*   batch = (const int*)d_in[3];
    int base = (n_in == 21) ? 5 : 4;   // n_graphs scalar may or may not be passed
    const float* lin_w = (const float*)d_in[base + 0];
    const float* lin_b = (const float*)d_in[base + 1];
    const float* mw1   = (const float*)d_in[base + 2];
    const float* mb1   = (const float*)d_in[base + 3];
    const float* mw2   = (const float*)d_in[base + 4];
    const float* mb2   = (const float*)d_in[base + 5];
    const float* bng   = (const float*)d_in[base + 6];
    const float* bnb   = (const float*)d_in[base + 7];
    const float* bnm   = (const float*)d_in[base + 8];
    const float* bnv   = (const float*)d_in[base + 9];
    const float* wih   = (const float*)d_in[base + 10];
    const float* whh   = (const float*)d_in[base + 11];
    const float* bih   = (const float*)d_in[base + 12];
    const float* bhh   = (const float*)d_in[base + 13];
    const float* ro_w  = (const float*)d_in[base + 14];
    const float* ro_b  = (const float*)d_in[base + 15];
    float* out = (float*)d_out;
    const int* src = eidx;
    const int* dst = eidx + NEDGES;

    float *hb, *pb, *sb, *gib, *ghb, *degb, *w2ib, *c2ib, *pkb, *pkbias;
    cudaGetSymbolAddress((void**)&hb, g_h);
    cudaGetSymbolAddress((void**)&pb, g_p);
    cudaGetSymbolAddress((void**)&sb, g_s);
    cudaGetSymbolAddress((void**)&gib, g_gi);
    cudaGetSymbolAddress((void**)&ghb, g_gh);
    cudaGetSymbolAddress((void**)&degb, g_deg);
    cudaGetSymbolAddress((void**)&w2ib, g_w2i);
    cudaGetSymbolAddress((void**)&c2ib, g_c2i);
    cudaGetSymbolAddress((void**)&pkb, g_packb);
    cudaGetSymbolAddress((void**)&pkbias, g_packbias);

    int gm = (NNODES + BM - 1) / BM;   // 391

    zero_misc_kernel<<<(NNODES + 255) / 256, 256>>>();
    deg_kernel<<<(NEDGES + 255) / 256, 256>>>(dst);
    pack_kernel<<<(NL * HID * 512 + 255) / 256, 256>>>(mw1, mb1, whh, bhh);
    w2i_kernel<<<NL * HID, 384>>>(mw2, wih);
    c2i_kernel<<<(NL * 384 + 255) / 256, 256>>>(mb2, wih);

    // h = relu(x @ lin_w + lin_b)
    sgemm128<<<dim3(gm, 2), 256>>>(x, lin_w, NNODES, 128, lin_b,
                                   hb, 128, nullptr, nullptr, nullptr, 1);

    for (int l = 0; l < NL; l++) {
        zero_s_kernel<<<(NNODES * HID / 4 + 255) / 256, 256>>>();
        // [P | GH] = h @ [W1a | whh^T] + [b1 | bhh]
        sgemm128<<<dim3(gm, 8), 256>>>(hb, pkb + l * HID * 512, NNODES, 512,
                                       pkbias + l * 512, pb, 128, ghb,
                                       nullptr, nullptr, 0);
        // S += relu(P[src] + ea@W1b) scattered to dst
        edge_kernel<<<1184, 256>>>(src, dst, eattr, mw1 + l * 144 * HID + 128 * HID);
        // GI = S @ W2i + deg*c2i + bih
        sgemm128<<<dim3(gm, 6), 256>>>(sb, w2ib + l * HID * 384, NNODES, 384,
                                       bih + l * 384, gib, 384, nullptr,
                                       degb, c2ib + l * 384, 0);
        // GRU gates + BN + residual, in-place h update
        gate_kernel<<<(NNODES * 32 + 255) / 256, 256>>>(bng + l * HID, bnb + l * HID,
                                                        bnm + l * HID, bnv + l * HID);
    }

    readout_kernel<<<(NNODES * 32 + 255) / 256, 256>>>(batch);
    final_kernel<<<NG, HID>>>(ro_w, ro_b, out);
    (void)in_sizes; (void)out_size;
}